// round 13
// baseline (speedup 1.0000x reference)
#include <cuda_runtime.h>
#include <cuda_fp16.h>
#include <math.h>
#include <stdint.h>
#include <stddef.h>

// Problem constants
#define Bz   8
#define Tz   4096
#define Dz   512
#define HIDz 1024
#define Kz   5
#define NTOK (Bz * Tz)          // 32768
#define CH   16                 // scan chunks
#define LCH  (Tz / CH)          // 256

// ---------------- scratch (static device globals; no runtime alloc) -------
__device__ __half g_xnh [(size_t)NTOK * Dz];   // LN1 output fp16
__device__ __half g_x1h [(size_t)NTOK * Dz];   // mid residual fp16
__device__ __half g_yloc[(size_t)NTOK * Dz];   // conv output fp16
__device__ __half g_ssh [(size_t)NTOK * Dz];   // retention states fp16
__device__ __half g_xn2h[(size_t)NTOK * Dz];   // LN2 output fp16
__device__ __half g_hh  [(size_t)NTOK * HIDz]; // MLP hidden fp16
__device__ float  g_lend [Bz * CH * Dz];
__device__ float  g_carry[Bz * CH * Dz];
__device__ __half g_wouth[Dz * Dz];
__device__ __half g_w1h [HIDz * Dz];
__device__ __half g_w2h [Dz * HIDz];

// =================== small helpers ===================
__device__ __forceinline__ uint32_t smem_u32(const void* p) {
    uint32_t a;
    asm("{ .reg .u64 t; cvta.to.shared.u64 t, %1; cvt.u32.u64 %0, t; }"
        : "=r"(a) : "l"(p));
    return a;
}

// =================== layernorm (fp32 in): one warp per token, fp16 out =====
__global__ void ln_kernel(const float* __restrict__ xin,
                          const float* __restrict__ gam,
                          const float* __restrict__ bet,
                          __half* __restrict__ outp) {
    int gw   = (blockIdx.x * blockDim.x + threadIdx.x) >> 5;  // token
    int lane = threadIdx.x & 31;
    const float4* xr = (const float4*)(xin + (size_t)gw * Dz);

    float4 v[4];
    #pragma unroll
    for (int i = 0; i < 4; i++) v[i] = xr[lane + 32 * i];

    float s = 0.0f, s2 = 0.0f;
    #pragma unroll
    for (int i = 0; i < 4; i++) {
        s  += v[i].x + v[i].y + v[i].z + v[i].w;
        s2 += v[i].x*v[i].x + v[i].y*v[i].y + v[i].z*v[i].z + v[i].w*v[i].w;
    }
    #pragma unroll
    for (int o = 16; o > 0; o >>= 1) {
        s  += __shfl_xor_sync(0xffffffffu, s,  o);
        s2 += __shfl_xor_sync(0xffffffffu, s2, o);
    }
    float mu  = s * (1.0f / Dz);
    float var = s2 * (1.0f / Dz) - mu * mu;
    float inv = rsqrtf(var + 1e-5f);

    __half2* ob = (__half2*)(outp + (size_t)gw * Dz);
    #pragma unroll
    for (int i = 0; i < 4; i++) {
        int c = lane + 32 * i;
        float4 gg = ((const float4*)gam)[c];
        float4 bb = ((const float4*)bet)[c];
        float o0 = (v[i].x - mu) * inv * gg.x + bb.x;
        float o1 = (v[i].y - mu) * inv * gg.y + bb.y;
        float o2 = (v[i].z - mu) * inv * gg.z + bb.z;
        float o3 = (v[i].w - mu) * inv * gg.w + bb.w;
        ob[c * 2 + 0] = __floats2half2_rn(o0, o1);
        ob[c * 2 + 1] = __floats2half2_rn(o2, o3);
    }
}

// =================== layernorm (fp16 in): one warp per token, fp16 out =====
__global__ void ln_kernel_h(const __half* __restrict__ xin,
                            const float* __restrict__ gam,
                            const float* __restrict__ bet,
                            __half* __restrict__ outp) {
    int gw   = (blockIdx.x * blockDim.x + threadIdx.x) >> 5;  // token
    int lane = threadIdx.x & 31;
    const uint4* xr = (const uint4*)(xin + (size_t)gw * Dz);  // 8 halves each

    float vals[16];
    #pragma unroll
    for (int i = 0; i < 2; i++) {
        uint4 u = xr[lane + 32 * i];
        const __half2* h = (const __half2*)&u;
        #pragma unroll
        for (int k = 0; k < 4; k++) {
            float2 f = __half22float2(h[k]);
            vals[i * 8 + k * 2 + 0] = f.x;
            vals[i * 8 + k * 2 + 1] = f.y;
        }
    }
    float s = 0.0f, s2 = 0.0f;
    #pragma unroll
    for (int k = 0; k < 16; k++) { s += vals[k]; s2 += vals[k] * vals[k]; }
    #pragma unroll
    for (int o = 16; o > 0; o >>= 1) {
        s  += __shfl_xor_sync(0xffffffffu, s,  o);
        s2 += __shfl_xor_sync(0xffffffffu, s2, o);
    }
    float mu  = s * (1.0f / Dz);
    float var = s2 * (1.0f / Dz) - mu * mu;
    float inv = rsqrtf(var + 1e-5f);

    const float2* g2 = (const float2*)gam;
    const float2* b2 = (const float2*)bet;
    __half2* ob = (__half2*)(outp + (size_t)gw * Dz);
    #pragma unroll
    for (int i = 0; i < 2; i++) {
        int p0 = (lane + 32 * i) * 4;      // half2-pair index base
        #pragma unroll
        for (int k = 0; k < 4; k++) {
            float2 gg = g2[p0 + k];
            float2 bb = b2[p0 + k];
            float o0 = (vals[i * 8 + k * 2 + 0] - mu) * inv * gg.x + bb.x;
            float o1 = (vals[i * 8 + k * 2 + 1] - mu) * inv * gg.y + bb.y;
            ob[p0 + k] = __floats2half2_rn(o0, o1);
        }
    }
}

// =================== chunked linear scan, half2-vectorized ===================
// thread owns channel pair d2 (d = 2*d2, 2*d2+1)
#define D2 (Dz / 2)   // 256

__global__ void scan_partial(const __half* __restrict__ xn,
                             const float* __restrict__ decay,
                             float* __restrict__ lend) {
    int idx = blockIdx.x * blockDim.x + threadIdx.x;   // Bz*CH*D2 threads
    int d2 = idx & (D2 - 1);
    int c  = (idx >> 8) & (CH - 1);
    int b  = idx >> 12;
    float2 dl = ((const float2*)decay)[d2];
    float a0 = 1.0f / (1.0f + expf(-dl.x));
    float a1 = 1.0f / (1.0f + expf(-dl.y));
    float na0 = 1.0f - a0, na1 = 1.0f - a1;
    const __half2* p = (const __half2*)(xn + ((size_t)(b * Tz + c * LCH)) * Dz) + d2;
    float s0 = 0.0f, s1 = 0.0f;
    #pragma unroll 8
    for (int t = 0; t < LCH; t++) {
        float2 f = __half22float2(p[(size_t)t * D2]);
        s0 = a0 * s0 + na0 * f.x;
        s1 = a1 * s1 + na1 * f.y;
    }
    ((float2*)lend)[(size_t)(b * CH + c) * D2 + d2] = make_float2(s0, s1);
}

__global__ void scan_carry(const float* __restrict__ lend,
                           const float* __restrict__ decay,
                           float* __restrict__ carry) {
    int idx = blockIdx.x * blockDim.x + threadIdx.x;   // B*Dz threads
    int d = idx & (Dz - 1);
    int b = idx >> 9;
    float a  = 1.0f / (1.0f + expf(-decay[d]));
    float aL = powf(a, (float)LCH);
    float s = 0.0f;
    #pragma unroll
    for (int c = 0; c < CH; c++) {
        int e = (b * CH + c) * Dz + d;
        carry[e] = s;
        s = aL * s + lend[e];
    }
}

// fused: final scan pass (fp16 ss out) + depthwise conv K=5 (fp16 yloc out)
// half2-vectorized: thread owns channel pair.
__global__ void scan_final_fused(const __half* __restrict__ xn,
                                 const float* __restrict__ decay,
                                 const float* __restrict__ carry,
                                 const float* __restrict__ cw,
                                 const float* __restrict__ cb,
                                 __half* __restrict__ ssh,
                                 __half* __restrict__ yloc) {
    int idx = blockIdx.x * blockDim.x + threadIdx.x;   // Bz*CH*D2 threads
    int d2 = idx & (D2 - 1);
    int c  = (idx >> 8) & (CH - 1);
    int b  = idx >> 12;
    int d0 = d2 * 2;
    float2 dl = ((const float2*)decay)[d2];
    float a0 = 1.0f / (1.0f + expf(-dl.x));
    float a1 = 1.0f / (1.0f + expf(-dl.y));
    float na0 = 1.0f - a0, na1 = 1.0f - a1;

    float w00 = cw[d0 * Kz + 0], w01 = cw[d0 * Kz + 1], w02 = cw[d0 * Kz + 2];
    float w03 = cw[d0 * Kz + 3], w04 = cw[d0 * Kz + 4];
    float w10 = cw[(d0 + 1) * Kz + 0], w11 = cw[(d0 + 1) * Kz + 1];
    float w12 = cw[(d0 + 1) * Kz + 2], w13 = cw[(d0 + 1) * Kz + 3];
    float w14 = cw[(d0 + 1) * Kz + 4];
    float bb0 = cb[d0], bb1 = cb[d0 + 1];

    int t0 = c * LCH;
    size_t base2 = ((size_t)(b * Tz + t0)) * D2 + d2;   // half2 units
    const __half2* p = (const __half2*)xn + base2;
    float2 xm2 = (t0 >= 2) ? __half22float2(p[-2 * (ptrdiff_t)D2]) : make_float2(0.f, 0.f);
    float2 xm1 = (t0 >= 1) ? __half22float2(p[-1 * (ptrdiff_t)D2]) : make_float2(0.f, 0.f);
    float2 x0  = __half22float2(p[0]);
    float2 x1v = __half22float2(p[(size_t)D2]);

    float2 cr = ((const float2*)carry)[(size_t)(b * CH + c) * D2 + d2];
    float s0 = cr.x, s1 = cr.y;

    __half2* pss = (__half2*)ssh + base2;
    __half2* pyl = (__half2*)yloc + base2;

    #pragma unroll 4
    for (int t = 0; t < LCH; t++) {
        int tg = t0 + t;
        float2 x2 = (tg + 2 < Tz) ? __half22float2(p[(size_t)(t + 2) * D2])
                                  : make_float2(0.f, 0.f);
        s0 = a0 * s0 + na0 * x0.x;
        s1 = a1 * s1 + na1 * x0.y;
        pss[(size_t)t * D2] = __floats2half2_rn(s0, s1);
        float y0 = bb0 + w00 * xm2.x + w01 * xm1.x + w02 * x0.x + w03 * x1v.x + w04 * x2.x;
        float y1 = bb1 + w10 * xm2.y + w11 * xm1.y + w12 * x0.y + w13 * x1v.y + w14 * x2.y;
        pyl[(size_t)t * D2] = __floats2half2_rn(y0, y1);
        xm2 = xm1; xm1 = x0; x0 = x1v; x1v = x2;
    }
}

// =================== weights fp32 -> fp16 (single launch) ===================
#define N0 (Dz * Dz)
#define N1 (HIDz * Dz)
#define N2 (Dz * HIDz)
__global__ void wconv(const float* __restrict__ w0, const float* __restrict__ w1,
                      const float* __restrict__ w2,
                      __half* __restrict__ o0, __half* __restrict__ o1,
                      __half* __restrict__ o2) {
    int i = blockIdx.x * blockDim.x + threadIdx.x;
    if (i < N0)                o0[i]           = __float2half(w0[i]);
    else if (i < N0 + N1)      o1[i - N0]      = __float2half(w1[i - N0]);
    else if (i < N0 + N1 + N2) o2[i - N0 - N1] = __float2half(w2[i - N0 - N1]);
}

// =================== mma.sync fp16 GEMM (BM=128, BN=128, BK=64, occ=2) =====
// C[M,Nc] = A[M,Kc] * W[Nc,Kc]^T.  Both operands K-major.
// 8 warps in 2(M)x4(N), warp tile 64x32. 3-stage cp.async pipeline.
// Mainloop order: ks=0 MMA batch first, then next-slab loads, then ks=1..3.
// EPI 0: out fp32  = acc + bias + res2h(fp16)            [final: x1h + mlp]
// EPI 1: out fp16  = gelu(acc + bias)                    [mlp hidden]
// EPI 2: out fp16  = acc + bias + res1(fp32) + res2h(fp16)  [x1h]
#define RSTRIDE 144u                       // smem bytes per row (128 data + 16 pad)
#define A_TILE_B (128u * RSTRIDE)          // 18432
#define W_TILE_B (128u * RSTRIDE)          // 18432
#define STAGE_B (A_TILE_B + W_TILE_B)      // 36864
#define NSTAGE 3
#define GEMM_SMEM (NSTAGE * STAGE_B)       // 110592 -> 2 CTAs/SM

__device__ __forceinline__ void ldm_x4(uint32_t* r, uint32_t addr) {
    asm volatile("ldmatrix.sync.aligned.m8n8.x4.shared.b16 {%0,%1,%2,%3}, [%4];"
                 : "=r"(r[0]), "=r"(r[1]), "=r"(r[2]), "=r"(r[3]) : "r"(addr));
}
__device__ __forceinline__ void mma16816(float* c, const uint32_t* a, const uint32_t* b) {
    asm volatile(
        "mma.sync.aligned.m16n8k16.row.col.f32.f16.f16.f32 "
        "{%0,%1,%2,%3}, {%4,%5,%6,%7}, {%8,%9}, {%0,%1,%2,%3};"
        : "+f"(c[0]), "+f"(c[1]), "+f"(c[2]), "+f"(c[3])
        : "r"(a[0]), "r"(a[1]), "r"(a[2]), "r"(a[3]), "r"(b[0]), "r"(b[1]));
}

template<int EPI, int Nc, int Kc>
__global__ void __launch_bounds__(256, 2)
gemm_mma(const __half* __restrict__ A, const __half* __restrict__ W,
         const float* __restrict__ bias,
         const float* __restrict__ res1, const __half* __restrict__ res2h,
         void* __restrict__ outp)
{
    extern __shared__ __align__(128) char smem[];
    const uint32_t sb = smem_u32(smem);
    const int tid  = threadIdx.x;
    const int lane = tid & 31;
    const int wid  = tid >> 5;
    const int warp_m = wid >> 2;        // 0..1  (x64 rows)
    const int warp_n = wid & 3;         // 0..3  (x32 cols)
    constexpr int NK = Kc >> 6;         // K / 64
    constexpr int NB = Nc >> 7;         // N / 128
    const int bn = blockIdx.x % NB;
    const int bm = blockIdx.x / NB;
    constexpr size_t Kb = (size_t)Kc * 2;   // row bytes in gmem

    const char* At = (const char*)A + ((size_t)bm << 7) * Kb;
    const char* Wt = (const char*)W + ((size_t)bn << 7) * Kb;

    // ---- async load of one k-slab (A:128 rows, W:128 rows, 64 k each) ----
    #define LOAD_STAGE(LS) do {                                               \
        uint32_t bufa = sb + (uint32_t)((LS) % NSTAGE) * STAGE_B;             \
        uint32_t bufw = bufa + A_TILE_B;                                      \
        size_t kb = (size_t)(LS) * 128;                                       \
        _Pragma("unroll")                                                     \
        for (int i = 0; i < 4; i++) {                                         \
            int idx = (i << 8) + tid;                                         \
            uint32_t r = (uint32_t)(idx >> 3);                                \
            uint32_t j = (uint32_t)(idx & 7) << 4;                            \
            asm volatile("cp.async.cg.shared.global [%0], [%1], 16;"          \
                :: "r"(bufa + r * RSTRIDE + j),                               \
                   "l"(At + (size_t)r * Kb + kb + j) : "memory");             \
        }                                                                     \
        _Pragma("unroll")                                                     \
        for (int i = 0; i < 4; i++) {                                         \
            int idx = (i << 8) + tid;                                         \
            uint32_t r = (uint32_t)(idx >> 3);                                \
            uint32_t j = (uint32_t)(idx & 7) << 4;                            \
            asm volatile("cp.async.cg.shared.global [%0], [%1], 16;"          \
                :: "r"(bufw + r * RSTRIDE + j),                               \
                   "l"(Wt + (size_t)r * Kb + kb + j) : "memory");             \
        }                                                                     \
        asm volatile("cp.async.commit_group;" ::: "memory");                  \
    } while (0)

    float acc[4][4][4];
    #pragma unroll
    for (int i = 0; i < 4; i++)
        #pragma unroll
        for (int j = 0; j < 4; j++)
            #pragma unroll
            for (int r = 0; r < 4; r++) acc[i][j][r] = 0.0f;

    LOAD_STAGE(0);
    LOAD_STAGE(1);

    // per-lane ldmatrix row/col offsets
    const uint32_t lrow = (uint32_t)(lane & 15);
    const uint32_t lcol = (uint32_t)(lane & 16);   // +16B for k+8 half

    #pragma unroll 1
    for (int kt = 0; kt < NK; kt++) {
        asm volatile("cp.async.wait_group 1;" ::: "memory");
        __syncthreads();

        uint32_t bufa = sb + (uint32_t)(kt % NSTAGE) * STAGE_B;
        uint32_t bufw = bufa + A_TILE_B;
        uint32_t abase = bufa + ((uint32_t)(warp_m * 64) + lrow) * RSTRIDE + lcol;
        uint32_t wbase = bufw + ((uint32_t)(warp_n * 32) + lrow) * RSTRIDE + lcol;

        // ---- ks = 0 first (start the tensor pipe before issuing loads) ----
        {
            uint32_t af[4][4];
            #pragma unroll
            for (int im = 0; im < 4; im++)
                ldm_x4(af[im], abase + (uint32_t)(im * 16) * RSTRIDE);
            uint32_t bf[4][2];
            #pragma unroll
            for (int hn = 0; hn < 2; hn++) {
                uint32_t t[4];
                ldm_x4(t, wbase + (uint32_t)(hn * 16) * RSTRIDE);
                bf[hn * 2 + 0][0] = t[0]; bf[hn * 2 + 0][1] = t[2];
                bf[hn * 2 + 1][0] = t[1]; bf[hn * 2 + 1][1] = t[3];
            }
            #pragma unroll
            for (int im = 0; im < 4; im++)
                #pragma unroll
                for (int j = 0; j < 4; j++)
                    mma16816(acc[im][j], af[im], bf[j]);
        }

        // ---- issue next slab loads, overlapped with remaining ks ----
        if (kt + 2 < NK) {
            LOAD_STAGE(kt + 2);
        } else {
            asm volatile("cp.async.commit_group;" ::: "memory");
        }

        #pragma unroll
        for (int ks = 1; ks < 4; ks++) {
            uint32_t kb2 = (uint32_t)ks * 32;
            uint32_t af[4][4];
            #pragma unroll
            for (int im = 0; im < 4; im++)
                ldm_x4(af[im], abase + (uint32_t)(im * 16) * RSTRIDE + kb2);
            uint32_t bf[4][2];
            #pragma unroll
            for (int hn = 0; hn < 2; hn++) {
                uint32_t t[4];
                ldm_x4(t, wbase + (uint32_t)(hn * 16) * RSTRIDE + kb2);
                bf[hn * 2 + 0][0] = t[0]; bf[hn * 2 + 0][1] = t[2];
                bf[hn * 2 + 1][0] = t[1]; bf[hn * 2 + 1][1] = t[3];
            }
            #pragma unroll
            for (int im = 0; im < 4; im++)
                #pragma unroll
                for (int j = 0; j < 4; j++)
                    mma16816(acc[im][j], af[im], bf[j]);
        }
        // top-of-loop barrier (after wait_group) orders buffer reuse.
    }
    #undef LOAD_STAGE

    // ---- epilogue ----
    const int g   = lane >> 2;
    const int tig = lane & 3;
    #pragma unroll
    for (int im = 0; im < 4; im++) {
        int gm = (bm << 7) + warp_m * 64 + im * 16 + g;
        #pragma unroll
        for (int j = 0; j < 4; j++) {
            int gn = (bn << 7) + warp_n * 32 + j * 8 + tig * 2;
            float bv0 = __ldg(&bias[gn]);
            float bv1 = __ldg(&bias[gn + 1]);
            #pragma unroll
            for (int half = 0; half < 2; half++) {
                int row = gm + half * 8;
                size_t off = (size_t)row * Nc + gn;
                float v0 = acc[im][j][half * 2 + 0] + bv0;
                float v1 = acc[im][j][half * 2 + 1] + bv1;
                if (EPI == 0) {
                    float2 r2 = __half22float2(*(const __half2*)(res2h + off));
                    *(float2*)((float*)outp + off) = make_float2(v0 + r2.x, v1 + r2.y);
                } else if (EPI == 2) {
                    float2 r1 = *(const float2*)(res1 + off);
                    float2 r2 = __half22float2(*(const __half2*)(res2h + off));
                    *(__half2*)((__half*)outp + off) =
                        __floats2half2_rn(v0 + r1.x + r2.x, v1 + r1.y + r2.y);
                } else {
                    float g0 = 0.5f * v0 * (1.0f + erff(v0 * 0.70710678118654752f));
                    float g1 = 0.5f * v1 * (1.0f + erff(v1 * 0.70710678118654752f));
                    *(__half2*)((__half*)outp + off) = __floats2half2_rn(g0, g1);
                }
            }
        }
    }
}

// =================== launcher ===================
extern "C" void kernel_launch(void* const* d_in, const int* in_sizes, int n_in,
                              void* d_out, int out_size) {
    const float* x       = (const float*)d_in[0];
    const float* decay   = (const float*)d_in[1];
    const float* W_out   = (const float*)d_in[2];
    const float* b_out   = (const float*)d_in[3];
    const float* conv_w  = (const float*)d_in[4];
    const float* conv_b  = (const float*)d_in[5];
    const float* ln1_g   = (const float*)d_in[6];
    const float* ln1_b   = (const float*)d_in[7];
    const float* ln2_g   = (const float*)d_in[8];
    const float* ln2_b   = (const float*)d_in[9];
    const float* W1      = (const float*)d_in[10];
    const float* b1      = (const float*)d_in[11];
    const float* W2      = (const float*)d_in[12];
    const float* b2      = (const float*)d_in[13];
    float* out = (float*)d_out;

    float *lend, *carry;
    __half *xnh, *x1h, *yloc, *ssh, *xn2h, *hh, *wouth, *w1h, *w2h;
    cudaGetSymbolAddress((void**)&xnh,   g_xnh);
    cudaGetSymbolAddress((void**)&x1h,   g_x1h);
    cudaGetSymbolAddress((void**)&yloc,  g_yloc);
    cudaGetSymbolAddress((void**)&lend,  g_lend);
    cudaGetSymbolAddress((void**)&carry, g_carry);
    cudaGetSymbolAddress((void**)&ssh,   g_ssh);
    cudaGetSymbolAddress((void**)&xn2h,  g_xn2h);
    cudaGetSymbolAddress((void**)&hh,    g_hh);
    cudaGetSymbolAddress((void**)&wouth, g_wouth);
    cudaGetSymbolAddress((void**)&w1h,   g_w1h);
    cudaGetSymbolAddress((void**)&w2h,   g_w2h);

    cudaFuncSetAttribute((const void*)gemm_mma<2, Dz, Dz>,
                         cudaFuncAttributeMaxDynamicSharedMemorySize, GEMM_SMEM);
    cudaFuncSetAttribute((const void*)gemm_mma<1, HIDz, Dz>,
                         cudaFuncAttributeMaxDynamicSharedMemorySize, GEMM_SMEM);
    cudaFuncSetAttribute((const void*)gemm_mma<0, Dz, HIDz>,
                         cudaFuncAttributeMaxDynamicSharedMemorySize, GEMM_SMEM);

    // weight conversion (single launch)
    wconv<<<(N0 + N1 + N2 + 255) / 256, 256>>>(W_out, W1, W2, wouth, w1h, w2h);

    // 1) xn = LN1(x)  (fp16)
    ln_kernel<<<NTOK / 8, 256>>>(x, ln1_g, ln1_b, xnh);

    // 2) retention scan (chunked, half2-vectorized) + fused depthwise conv
    scan_partial<<<(Bz * CH * D2) / 256, 256>>>(xnh, decay, lend);
    scan_carry<<<(Bz * Dz) / 256, 256>>>(lend, decay, carry);
    scan_final_fused<<<(Bz * CH * D2) / 256, 256>>>(xnh, decay, carry,
                                                    conv_w, conv_b, ssh, yloc);

    // 3) x1h = fp16(x + yloc + ss @ W_out^T + b_out)
    gemm_mma<2, Dz, Dz><<<(NTOK / 128) * (Dz / 128), 256, GEMM_SMEM>>>(
        ssh, wouth, b_out, x, yloc, x1h);

    // 4) xn2 = LN2(x1h)  (fp16 in/out)
    ln_kernel_h<<<NTOK / 8, 256>>>(x1h, ln2_g, ln2_b, xn2h);

    // 5) h = gelu(xn2 @ W1^T + b1)  (fp16 out)
    gemm_mma<1, HIDz, Dz><<<(NTOK / 128) * (HIDz / 128), 256, GEMM_SMEM>>>(
        xn2h, w1h, b1, nullptr, nullptr, hh);

    // 6) out = x1h + h @ W2^T + b2  (fp32 out)
    gemm_mma<0, Dz, HIDz><<<(NTOK / 128) * (Dz / 128), 256, GEMM_SMEM>>>(
        hh, w2h, b2, nullptr, x1h, out);
}

// round 14
// speedup vs baseline: 1.0634x; 1.0634x over previous
#include <cuda_runtime.h>
#include <cuda_fp16.h>
#include <math.h>
#include <stdint.h>
#include <stddef.h>

// Problem constants
#define Bz   8
#define Tz   4096
#define Dz   512
#define HIDz 1024
#define Kz   5
#define NTOK (Bz * Tz)          // 32768
#define CH   32                 // scan chunks (half2 scan keeps 65536 threads)
#define LCH  (Tz / CH)          // 128
#define D2   (Dz / 2)           // 256 channel pairs

// ---------------- scratch (static device globals; no runtime alloc) -------
__device__ __half g_xnh [(size_t)NTOK * Dz];   // LN1 output fp16
__device__ __half g_x1h [(size_t)NTOK * Dz];   // mid residual fp16
__device__ __half g_yloc[(size_t)NTOK * Dz];   // conv output fp16
__device__ __half g_ssh [(size_t)NTOK * Dz];   // retention states fp16
__device__ __half g_xn2h[(size_t)NTOK * Dz];   // LN2 output fp16
__device__ __half g_hh  [(size_t)NTOK * HIDz]; // MLP hidden fp16
__device__ float  g_lend [Bz * CH * Dz];
__device__ float  g_carry[Bz * CH * Dz];
__device__ __half g_wouth[Dz * Dz];
__device__ __half g_w1h [HIDz * Dz];
__device__ __half g_w2h [Dz * HIDz];

// =================== small helpers ===================
__device__ __forceinline__ uint32_t smem_u32(const void* p) {
    uint32_t a;
    asm("{ .reg .u64 t; cvta.to.shared.u64 t, %1; cvt.u32.u64 %0, t; }"
        : "=r"(a) : "l"(p));
    return a;
}

// =================== layernorm (fp32 in): one warp per token, fp16 out =====
__global__ void ln_kernel(const float* __restrict__ xin,
                          const float* __restrict__ gam,
                          const float* __restrict__ bet,
                          __half* __restrict__ outp) {
    int gw   = (blockIdx.x * blockDim.x + threadIdx.x) >> 5;  // token
    int lane = threadIdx.x & 31;
    const float4* xr = (const float4*)(xin + (size_t)gw * Dz);

    float4 v[4];
    #pragma unroll
    for (int i = 0; i < 4; i++) v[i] = xr[lane + 32 * i];

    float s = 0.0f, s2 = 0.0f;
    #pragma unroll
    for (int i = 0; i < 4; i++) {
        s  += v[i].x + v[i].y + v[i].z + v[i].w;
        s2 += v[i].x*v[i].x + v[i].y*v[i].y + v[i].z*v[i].z + v[i].w*v[i].w;
    }
    #pragma unroll
    for (int o = 16; o > 0; o >>= 1) {
        s  += __shfl_xor_sync(0xffffffffu, s,  o);
        s2 += __shfl_xor_sync(0xffffffffu, s2, o);
    }
    float mu  = s * (1.0f / Dz);
    float var = s2 * (1.0f / Dz) - mu * mu;
    float inv = rsqrtf(var + 1e-5f);

    __half2* ob = (__half2*)(outp + (size_t)gw * Dz);
    #pragma unroll
    for (int i = 0; i < 4; i++) {
        int c = lane + 32 * i;
        float4 gg = ((const float4*)gam)[c];
        float4 bb = ((const float4*)bet)[c];
        float o0 = (v[i].x - mu) * inv * gg.x + bb.x;
        float o1 = (v[i].y - mu) * inv * gg.y + bb.y;
        float o2 = (v[i].z - mu) * inv * gg.z + bb.z;
        float o3 = (v[i].w - mu) * inv * gg.w + bb.w;
        ob[c * 2 + 0] = __floats2half2_rn(o0, o1);
        ob[c * 2 + 1] = __floats2half2_rn(o2, o3);
    }
}

// =================== layernorm (fp16 in): one warp per token, fp16 out =====
__global__ void ln_kernel_h(const __half* __restrict__ xin,
                            const float* __restrict__ gam,
                            const float* __restrict__ bet,
                            __half* __restrict__ outp) {
    int gw   = (blockIdx.x * blockDim.x + threadIdx.x) >> 5;  // token
    int lane = threadIdx.x & 31;
    const uint4* xr = (const uint4*)(xin + (size_t)gw * Dz);  // 8 halves each

    float vals[16];
    #pragma unroll
    for (int i = 0; i < 2; i++) {
        uint4 u = xr[lane + 32 * i];
        const __half2* h = (const __half2*)&u;
        #pragma unroll
        for (int k = 0; k < 4; k++) {
            float2 f = __half22float2(h[k]);
            vals[i * 8 + k * 2 + 0] = f.x;
            vals[i * 8 + k * 2 + 1] = f.y;
        }
    }
    float s = 0.0f, s2 = 0.0f;
    #pragma unroll
    for (int k = 0; k < 16; k++) { s += vals[k]; s2 += vals[k] * vals[k]; }
    #pragma unroll
    for (int o = 16; o > 0; o >>= 1) {
        s  += __shfl_xor_sync(0xffffffffu, s,  o);
        s2 += __shfl_xor_sync(0xffffffffu, s2, o);
    }
    float mu  = s * (1.0f / Dz);
    float var = s2 * (1.0f / Dz) - mu * mu;
    float inv = rsqrtf(var + 1e-5f);

    const float2* g2 = (const float2*)gam;
    const float2* b2 = (const float2*)bet;
    __half2* ob = (__half2*)(outp + (size_t)gw * Dz);
    #pragma unroll
    for (int i = 0; i < 2; i++) {
        int p0 = (lane + 32 * i) * 4;      // half2-pair index base
        #pragma unroll
        for (int k = 0; k < 4; k++) {
            float2 gg = g2[p0 + k];
            float2 bb = b2[p0 + k];
            float o0 = (vals[i * 8 + k * 2 + 0] - mu) * inv * gg.x + bb.x;
            float o1 = (vals[i * 8 + k * 2 + 1] - mu) * inv * gg.y + bb.y;
            ob[p0 + k] = __floats2half2_rn(o0, o1);
        }
    }
}

// =================== chunked linear scan, half2-vectorized, CH=32 ==========
// thread owns channel pair d2 (d = 2*d2, 2*d2+1); 65536 threads total.
__global__ void scan_partial(const __half* __restrict__ xn,
                             const float* __restrict__ decay,
                             float* __restrict__ lend) {
    int idx = blockIdx.x * blockDim.x + threadIdx.x;   // Bz*CH*D2 threads
    int d2 = idx & (D2 - 1);
    int c  = (idx >> 8) & (CH - 1);
    int b  = idx >> 13;
    float2 dl = ((const float2*)decay)[d2];
    float a0 = 1.0f / (1.0f + expf(-dl.x));
    float a1 = 1.0f / (1.0f + expf(-dl.y));
    float na0 = 1.0f - a0, na1 = 1.0f - a1;
    const __half2* p = (const __half2*)(xn + ((size_t)(b * Tz + c * LCH)) * Dz) + d2;
    float s0 = 0.0f, s1 = 0.0f;
    #pragma unroll 8
    for (int t = 0; t < LCH; t++) {
        float2 f = __half22float2(p[(size_t)t * D2]);
        s0 = a0 * s0 + na0 * f.x;
        s1 = a1 * s1 + na1 * f.y;
    }
    ((float2*)lend)[(size_t)(b * CH + c) * D2 + d2] = make_float2(s0, s1);
}

__global__ void scan_carry(const float* __restrict__ lend,
                           const float* __restrict__ decay,
                           float* __restrict__ carry) {
    int idx = blockIdx.x * blockDim.x + threadIdx.x;   // B*Dz threads
    int d = idx & (Dz - 1);
    int b = idx >> 9;
    float a  = 1.0f / (1.0f + expf(-decay[d]));
    float aL = powf(a, (float)LCH);
    float s = 0.0f;
    #pragma unroll
    for (int c = 0; c < CH; c++) {
        int e = (b * CH + c) * Dz + d;
        carry[e] = s;
        s = aL * s + lend[e];
    }
}

// fused: final scan pass (fp16 ss out) + depthwise conv K=5 (fp16 yloc out)
// half2-vectorized: thread owns channel pair.
__global__ void scan_final_fused(const __half* __restrict__ xn,
                                 const float* __restrict__ decay,
                                 const float* __restrict__ carry,
                                 const float* __restrict__ cw,
                                 const float* __restrict__ cb,
                                 __half* __restrict__ ssh,
                                 __half* __restrict__ yloc) {
    int idx = blockIdx.x * blockDim.x + threadIdx.x;   // Bz*CH*D2 threads
    int d2 = idx & (D2 - 1);
    int c  = (idx >> 8) & (CH - 1);
    int b  = idx >> 13;
    int d0 = d2 * 2;
    float2 dl = ((const float2*)decay)[d2];
    float a0 = 1.0f / (1.0f + expf(-dl.x));
    float a1 = 1.0f / (1.0f + expf(-dl.y));
    float na0 = 1.0f - a0, na1 = 1.0f - a1;

    float w00 = cw[d0 * Kz + 0], w01 = cw[d0 * Kz + 1], w02 = cw[d0 * Kz + 2];
    float w03 = cw[d0 * Kz + 3], w04 = cw[d0 * Kz + 4];
    float w10 = cw[(d0 + 1) * Kz + 0], w11 = cw[(d0 + 1) * Kz + 1];
    float w12 = cw[(d0 + 1) * Kz + 2], w13 = cw[(d0 + 1) * Kz + 3];
    float w14 = cw[(d0 + 1) * Kz + 4];
    float bb0 = cb[d0], bb1 = cb[d0 + 1];

    int t0 = c * LCH;
    size_t base2 = ((size_t)(b * Tz + t0)) * D2 + d2;   // half2 units
    const __half2* p = (const __half2*)xn + base2;
    float2 xm2 = (t0 >= 2) ? __half22float2(p[-2 * (ptrdiff_t)D2]) : make_float2(0.f, 0.f);
    float2 xm1 = (t0 >= 1) ? __half22float2(p[-1 * (ptrdiff_t)D2]) : make_float2(0.f, 0.f);
    float2 x0  = __half22float2(p[0]);
    float2 x1v = __half22float2(p[(size_t)D2]);   // t0+1 < Tz always (t0 <= Tz-LCH)

    float2 cr = ((const float2*)carry)[(size_t)(b * CH + c) * D2 + d2];
    float s0 = cr.x, s1 = cr.y;

    __half2* pss = (__half2*)ssh + base2;
    __half2* pyl = (__half2*)yloc + base2;

    #pragma unroll 4
    for (int t = 0; t < LCH; t++) {
        int tg = t0 + t;
        float2 x2 = (tg + 2 < Tz) ? __half22float2(p[(size_t)(t + 2) * D2])
                                  : make_float2(0.f, 0.f);
        s0 = a0 * s0 + na0 * x0.x;
        s1 = a1 * s1 + na1 * x0.y;
        pss[(size_t)t * D2] = __floats2half2_rn(s0, s1);
        float y0 = bb0 + w00 * xm2.x + w01 * xm1.x + w02 * x0.x + w03 * x1v.x + w04 * x2.x;
        float y1 = bb1 + w10 * xm2.y + w11 * xm1.y + w12 * x0.y + w13 * x1v.y + w14 * x2.y;
        pyl[(size_t)t * D2] = __floats2half2_rn(y0, y1);
        xm2 = xm1; xm1 = x0; x0 = x1v; x1v = x2;
    }
}

// =================== weights fp32 -> fp16 (single launch) ===================
#define N0 (Dz * Dz)
#define N1 (HIDz * Dz)
#define N2 (Dz * HIDz)
__global__ void wconv(const float* __restrict__ w0, const float* __restrict__ w1,
                      const float* __restrict__ w2,
                      __half* __restrict__ o0, __half* __restrict__ o1,
                      __half* __restrict__ o2) {
    int i = blockIdx.x * blockDim.x + threadIdx.x;
    if (i < N0)                o0[i]           = __float2half(w0[i]);
    else if (i < N0 + N1)      o1[i - N0]      = __float2half(w1[i - N0]);
    else if (i < N0 + N1 + N2) o2[i - N0 - N1] = __float2half(w2[i - N0 - N1]);
}

// =================== mma.sync fp16 GEMM (BM=128, BN=128, BK=64, occ=2) =====
// C[M,Nc] = A[M,Kc] * W[Nc,Kc]^T.  Both operands K-major.
// 8 warps in 2(M)x4(N), warp tile 64x32. 3-stage cp.async pipeline.
// Mainloop order: ks=0 MMA batch first, then next-slab loads, then ks=1..3.
// EPI 0: out fp32  = acc + bias + res2h(fp16)            [final: x1h + mlp]
// EPI 1: out fp16  = gelu(acc + bias)                    [mlp hidden]
// EPI 2: out fp16  = acc + bias + res1(fp32) + res2h(fp16)  [x1h]
#define RSTRIDE 144u                       // smem bytes per row (128 data + 16 pad)
#define A_TILE_B (128u * RSTRIDE)          // 18432
#define W_TILE_B (128u * RSTRIDE)          // 18432
#define STAGE_B (A_TILE_B + W_TILE_B)      // 36864
#define NSTAGE 3
#define GEMM_SMEM (NSTAGE * STAGE_B)       // 110592 -> 2 CTAs/SM

__device__ __forceinline__ void ldm_x4(uint32_t* r, uint32_t addr) {
    asm volatile("ldmatrix.sync.aligned.m8n8.x4.shared.b16 {%0,%1,%2,%3}, [%4];"
                 : "=r"(r[0]), "=r"(r[1]), "=r"(r[2]), "=r"(r[3]) : "r"(addr));
}
__device__ __forceinline__ void mma16816(float* c, const uint32_t* a, const uint32_t* b) {
    asm volatile(
        "mma.sync.aligned.m16n8k16.row.col.f32.f16.f16.f32 "
        "{%0,%1,%2,%3}, {%4,%5,%6,%7}, {%8,%9}, {%0,%1,%2,%3};"
        : "+f"(c[0]), "+f"(c[1]), "+f"(c[2]), "+f"(c[3])
        : "r"(a[0]), "r"(a[1]), "r"(a[2]), "r"(a[3]), "r"(b[0]), "r"(b[1]));
}

template<int EPI, int Nc, int Kc>
__global__ void __launch_bounds__(256, 2)
gemm_mma(const __half* __restrict__ A, const __half* __restrict__ W,
         const float* __restrict__ bias,
         const float* __restrict__ res1, const __half* __restrict__ res2h,
         void* __restrict__ outp)
{
    extern __shared__ __align__(128) char smem[];
    const uint32_t sb = smem_u32(smem);
    const int tid  = threadIdx.x;
    const int lane = tid & 31;
    const int wid  = tid >> 5;
    const int warp_m = wid >> 2;        // 0..1  (x64 rows)
    const int warp_n = wid & 3;         // 0..3  (x32 cols)
    constexpr int NK = Kc >> 6;         // K / 64
    constexpr int NB = Nc >> 7;         // N / 128
    const int bn = blockIdx.x % NB;
    const int bm = blockIdx.x / NB;
    constexpr size_t Kb = (size_t)Kc * 2;   // row bytes in gmem

    const char* At = (const char*)A + ((size_t)bm << 7) * Kb;
    const char* Wt = (const char*)W + ((size_t)bn << 7) * Kb;

    // ---- async load of one k-slab (A:128 rows, W:128 rows, 64 k each) ----
    #define LOAD_STAGE(LS) do {                                               \
        uint32_t bufa = sb + (uint32_t)((LS) % NSTAGE) * STAGE_B;             \
        uint32_t bufw = bufa + A_TILE_B;                                      \
        size_t kb = (size_t)(LS) * 128;                                       \
        _Pragma("unroll")                                                     \
        for (int i = 0; i < 4; i++) {                                         \
            int idx = (i << 8) + tid;                                         \
            uint32_t r = (uint32_t)(idx >> 3);                                \
            uint32_t j = (uint32_t)(idx & 7) << 4;                            \
            asm volatile("cp.async.cg.shared.global [%0], [%1], 16;"          \
                :: "r"(bufa + r * RSTRIDE + j),                               \
                   "l"(At + (size_t)r * Kb + kb + j) : "memory");             \
        }                                                                     \
        _Pragma("unroll")                                                     \
        for (int i = 0; i < 4; i++) {                                         \
            int idx = (i << 8) + tid;                                         \
            uint32_t r = (uint32_t)(idx >> 3);                                \
            uint32_t j = (uint32_t)(idx & 7) << 4;                            \
            asm volatile("cp.async.cg.shared.global [%0], [%1], 16;"          \
                :: "r"(bufw + r * RSTRIDE + j),                               \
                   "l"(Wt + (size_t)r * Kb + kb + j) : "memory");             \
        }                                                                     \
        asm volatile("cp.async.commit_group;" ::: "memory");                  \
    } while (0)

    float acc[4][4][4];
    #pragma unroll
    for (int i = 0; i < 4; i++)
        #pragma unroll
        for (int j = 0; j < 4; j++)
            #pragma unroll
            for (int r = 0; r < 4; r++) acc[i][j][r] = 0.0f;

    LOAD_STAGE(0);
    LOAD_STAGE(1);

    // per-lane ldmatrix row/col offsets
    const uint32_t lrow = (uint32_t)(lane & 15);
    const uint32_t lcol = (uint32_t)(lane & 16);   // +16B for k+8 half

    #pragma unroll 1
    for (int kt = 0; kt < NK; kt++) {
        asm volatile("cp.async.wait_group 1;" ::: "memory");
        __syncthreads();

        uint32_t bufa = sb + (uint32_t)(kt % NSTAGE) * STAGE_B;
        uint32_t bufw = bufa + A_TILE_B;
        uint32_t abase = bufa + ((uint32_t)(warp_m * 64) + lrow) * RSTRIDE + lcol;
        uint32_t wbase = bufw + ((uint32_t)(warp_n * 32) + lrow) * RSTRIDE + lcol;

        // ---- ks = 0 first (start the tensor pipe before issuing loads) ----
        {
            uint32_t af[4][4];
            #pragma unroll
            for (int im = 0; im < 4; im++)
                ldm_x4(af[im], abase + (uint32_t)(im * 16) * RSTRIDE);
            uint32_t bf[4][2];
            #pragma unroll
            for (int hn = 0; hn < 2; hn++) {
                uint32_t t[4];
                ldm_x4(t, wbase + (uint32_t)(hn * 16) * RSTRIDE);
                bf[hn * 2 + 0][0] = t[0]; bf[hn * 2 + 0][1] = t[2];
                bf[hn * 2 + 1][0] = t[1]; bf[hn * 2 + 1][1] = t[3];
            }
            #pragma unroll
            for (int im = 0; im < 4; im++)
                #pragma unroll
                for (int j = 0; j < 4; j++)
                    mma16816(acc[im][j], af[im], bf[j]);
        }

        // ---- issue next slab loads, overlapped with remaining ks ----
        if (kt + 2 < NK) {
            LOAD_STAGE(kt + 2);
        } else {
            asm volatile("cp.async.commit_group;" ::: "memory");
        }

        #pragma unroll
        for (int ks = 1; ks < 4; ks++) {
            uint32_t kb2 = (uint32_t)ks * 32;
            uint32_t af[4][4];
            #pragma unroll
            for (int im = 0; im < 4; im++)
                ldm_x4(af[im], abase + (uint32_t)(im * 16) * RSTRIDE + kb2);
            uint32_t bf[4][2];
            #pragma unroll
            for (int hn = 0; hn < 2; hn++) {
                uint32_t t[4];
                ldm_x4(t, wbase + (uint32_t)(hn * 16) * RSTRIDE + kb2);
                bf[hn * 2 + 0][0] = t[0]; bf[hn * 2 + 0][1] = t[2];
                bf[hn * 2 + 1][0] = t[1]; bf[hn * 2 + 1][1] = t[3];
            }
            #pragma unroll
            for (int im = 0; im < 4; im++)
                #pragma unroll
                for (int j = 0; j < 4; j++)
                    mma16816(acc[im][j], af[im], bf[j]);
        }
        // top-of-loop barrier (after wait_group) orders buffer reuse.
    }
    #undef LOAD_STAGE

    // ---- epilogue ----
    const int g   = lane >> 2;
    const int tig = lane & 3;
    #pragma unroll
    for (int im = 0; im < 4; im++) {
        int gm = (bm << 7) + warp_m * 64 + im * 16 + g;
        #pragma unroll
        for (int j = 0; j < 4; j++) {
            int gn = (bn << 7) + warp_n * 32 + j * 8 + tig * 2;
            float bv0 = __ldg(&bias[gn]);
            float bv1 = __ldg(&bias[gn + 1]);
            #pragma unroll
            for (int half = 0; half < 2; half++) {
                int row = gm + half * 8;
                size_t off = (size_t)row * Nc + gn;
                float v0 = acc[im][j][half * 2 + 0] + bv0;
                float v1 = acc[im][j][half * 2 + 1] + bv1;
                if (EPI == 0) {
                    float2 r2 = __half22float2(*(const __half2*)(res2h + off));
                    *(float2*)((float*)outp + off) = make_float2(v0 + r2.x, v1 + r2.y);
                } else if (EPI == 2) {
                    float2 r1 = *(const float2*)(res1 + off);
                    float2 r2 = __half22float2(*(const __half2*)(res2h + off));
                    *(__half2*)((__half*)outp + off) =
                        __floats2half2_rn(v0 + r1.x + r2.x, v1 + r1.y + r2.y);
                } else {
                    float g0 = 0.5f * v0 * (1.0f + erff(v0 * 0.70710678118654752f));
                    float g1 = 0.5f * v1 * (1.0f + erff(v1 * 0.70710678118654752f));
                    *(__half2*)((__half*)outp + off) = __floats2half2_rn(g0, g1);
                }
            }
        }
    }
}

// =================== launcher ===================
extern "C" void kernel_launch(void* const* d_in, const int* in_sizes, int n_in,
                              void* d_out, int out_size) {
    const float* x       = (const float*)d_in[0];
    const float* decay   = (const float*)d_in[1];
    const float* W_out   = (const float*)d_in[2];
    const float* b_out   = (const float*)d_in[3];
    const float* conv_w  = (const float*)d_in[4];
    const float* conv_b  = (const float*)d_in[5];
    const float* ln1_g   = (const float*)d_in[6];
    const float* ln1_b   = (const float*)d_in[7];
    const float* ln2_g   = (const float*)d_in[8];
    const float* ln2_b   = (const float*)d_in[9];
    const float* W1      = (const float*)d_in[10];
    const float* b1      = (const float*)d_in[11];
    const float* W2      = (const float*)d_in[12];
    const float* b2      = (const float*)d_in[13];
    float* out = (float*)d_out;

    float *lend, *carry;
    __half *xnh, *x1h, *yloc, *ssh, *xn2h, *hh, *wouth, *w1h, *w2h;
    cudaGetSymbolAddress((void**)&xnh,   g_xnh);
    cudaGetSymbolAddress((void**)&x1h,   g_x1h);
    cudaGetSymbolAddress((void**)&yloc,  g_yloc);
    cudaGetSymbolAddress((void**)&lend,  g_lend);
    cudaGetSymbolAddress((void**)&carry, g_carry);
    cudaGetSymbolAddress((void**)&ssh,   g_ssh);
    cudaGetSymbolAddress((void**)&xn2h,  g_xn2h);
    cudaGetSymbolAddress((void**)&hh,    g_hh);
    cudaGetSymbolAddress((void**)&wouth, g_wouth);
    cudaGetSymbolAddress((void**)&w1h,   g_w1h);
    cudaGetSymbolAddress((void**)&w2h,   g_w2h);

    cudaFuncSetAttribute((const void*)gemm_mma<2, Dz, Dz>,
                         cudaFuncAttributeMaxDynamicSharedMemorySize, GEMM_SMEM);
    cudaFuncSetAttribute((const void*)gemm_mma<1, HIDz, Dz>,
                         cudaFuncAttributeMaxDynamicSharedMemorySize, GEMM_SMEM);
    cudaFuncSetAttribute((const void*)gemm_mma<0, Dz, HIDz>,
                         cudaFuncAttributeMaxDynamicSharedMemorySize, GEMM_SMEM);

    // weight conversion (single launch)
    wconv<<<(N0 + N1 + N2 + 255) / 256, 256>>>(W_out, W1, W2, wouth, w1h, w2h);

    // 1) xn = LN1(x)  (fp16)
    ln_kernel<<<NTOK / 8, 256>>>(x, ln1_g, ln1_b, xnh);

    // 2) retention scan (chunked CH=32, half2-vectorized, full grid) + conv
    scan_partial<<<(Bz * CH * D2) / 256, 256>>>(xnh, decay, lend);
    scan_carry<<<(Bz * Dz) / 256, 256>>>(lend, decay, carry);
    scan_final_fused<<<(Bz * CH * D2) / 256, 256>>>(xnh, decay, carry,
                                                    conv_w, conv_b, ssh, yloc);

    // 3) x1h = fp16(x + yloc + ss @ W_out^T + b_out)
    gemm_mma<2, Dz, Dz><<<(NTOK / 128) * (Dz / 128), 256, GEMM_SMEM>>>(
        ssh, wouth, b_out, x, yloc, x1h);

    // 4) xn2 = LN2(x1h)  (fp16 in/out)
    ln_kernel_h<<<NTOK / 8, 256>>>(x1h, ln2_g, ln2_b, xn2h);

    // 5) h = gelu(xn2 @ W1^T + b1)  (fp16 out)
    gemm_mma<1, HIDz, Dz><<<(NTOK / 128) * (HIDz / 128), 256, GEMM_SMEM>>>(
        xn2h, w1h, b1, nullptr, nullptr, hh);

    // 6) out = x1h + h @ W2^T + b2  (fp32 out)
    gemm_mma<0, Dz, HIDz><<<(NTOK / 128) * (Dz / 128), 256, GEMM_SMEM>>>(
        hh, w2h, b2, nullptr, x1h, out);
}

// round 15
// speedup vs baseline: 1.1014x; 1.0357x over previous
#include <cuda_runtime.h>
#include <cuda_fp16.h>
#include <math.h>
#include <stdint.h>
#include <stddef.h>

// Problem constants
#define Bz   8
#define Tz   4096
#define Dz   512
#define HIDz 1024
#define Kz   5
#define NTOK (Bz * Tz)          // 32768
#define CH   32                 // scan chunks (half2 scan keeps 65536 threads)
#define LCH  (Tz / CH)          // 128
#define D2   (Dz / 2)           // 256 channel pairs

// ---------------- scratch (static device globals; no runtime alloc) -------
__device__ __half g_xnh [(size_t)NTOK * Dz];   // LN1 output fp16
__device__ __half g_xh  [(size_t)NTOK * Dz];   // x residual fp16
__device__ __half g_x1h [(size_t)NTOK * Dz];   // mid residual fp16
__device__ __half g_yloc[(size_t)NTOK * Dz];   // conv output fp16
__device__ __half g_ssh [(size_t)NTOK * Dz];   // retention states fp16
__device__ __half g_xn2h[(size_t)NTOK * Dz];   // LN2 output fp16
__device__ __half g_hh  [(size_t)NTOK * HIDz]; // MLP hidden fp16
__device__ float  g_lend [Bz * CH * Dz];
__device__ float  g_carry[Bz * CH * Dz];
__device__ __half g_wouth[Dz * Dz];
__device__ __half g_w1h [HIDz * Dz];
__device__ __half g_w2h [Dz * HIDz];

// =================== small helpers ===================
__device__ __forceinline__ uint32_t smem_u32(const void* p) {
    uint32_t a;
    asm("{ .reg .u64 t; cvta.to.shared.u64 t, %1; cvt.u32.u64 %0, t; }"
        : "=r"(a) : "l"(p));
    return a;
}

// ====== layernorm (fp32 in): one warp per token, fp16 out + fp16 copy of x =
__global__ void ln_kernel(const float* __restrict__ xin,
                          const float* __restrict__ gam,
                          const float* __restrict__ bet,
                          __half* __restrict__ outp,
                          __half* __restrict__ xcopy) {
    int gw   = (blockIdx.x * blockDim.x + threadIdx.x) >> 5;  // token
    int lane = threadIdx.x & 31;
    const float4* xr = (const float4*)(xin + (size_t)gw * Dz);

    float4 v[4];
    #pragma unroll
    for (int i = 0; i < 4; i++) v[i] = xr[lane + 32 * i];

    float s = 0.0f, s2 = 0.0f;
    #pragma unroll
    for (int i = 0; i < 4; i++) {
        s  += v[i].x + v[i].y + v[i].z + v[i].w;
        s2 += v[i].x*v[i].x + v[i].y*v[i].y + v[i].z*v[i].z + v[i].w*v[i].w;
    }
    #pragma unroll
    for (int o = 16; o > 0; o >>= 1) {
        s  += __shfl_xor_sync(0xffffffffu, s,  o);
        s2 += __shfl_xor_sync(0xffffffffu, s2, o);
    }
    float mu  = s * (1.0f / Dz);
    float var = s2 * (1.0f / Dz) - mu * mu;
    float inv = rsqrtf(var + 1e-5f);

    __half2* ob = (__half2*)(outp + (size_t)gw * Dz);
    __half2* xb = (__half2*)(xcopy + (size_t)gw * Dz);
    #pragma unroll
    for (int i = 0; i < 4; i++) {
        int c = lane + 32 * i;
        float4 gg = ((const float4*)gam)[c];
        float4 bb = ((const float4*)bet)[c];
        float o0 = (v[i].x - mu) * inv * gg.x + bb.x;
        float o1 = (v[i].y - mu) * inv * gg.y + bb.y;
        float o2 = (v[i].z - mu) * inv * gg.z + bb.z;
        float o3 = (v[i].w - mu) * inv * gg.w + bb.w;
        ob[c * 2 + 0] = __floats2half2_rn(o0, o1);
        ob[c * 2 + 1] = __floats2half2_rn(o2, o3);
        xb[c * 2 + 0] = __floats2half2_rn(v[i].x, v[i].y);
        xb[c * 2 + 1] = __floats2half2_rn(v[i].z, v[i].w);
    }
}

// =================== layernorm (fp16 in): one warp per token, fp16 out =====
__global__ void ln_kernel_h(const __half* __restrict__ xin,
                            const float* __restrict__ gam,
                            const float* __restrict__ bet,
                            __half* __restrict__ outp) {
    int gw   = (blockIdx.x * blockDim.x + threadIdx.x) >> 5;  // token
    int lane = threadIdx.x & 31;
    const uint4* xr = (const uint4*)(xin + (size_t)gw * Dz);  // 8 halves each

    float vals[16];
    #pragma unroll
    for (int i = 0; i < 2; i++) {
        uint4 u = xr[lane + 32 * i];
        const __half2* h = (const __half2*)&u;
        #pragma unroll
        for (int k = 0; k < 4; k++) {
            float2 f = __half22float2(h[k]);
            vals[i * 8 + k * 2 + 0] = f.x;
            vals[i * 8 + k * 2 + 1] = f.y;
        }
    }
    float s = 0.0f, s2 = 0.0f;
    #pragma unroll
    for (int k = 0; k < 16; k++) { s += vals[k]; s2 += vals[k] * vals[k]; }
    #pragma unroll
    for (int o = 16; o > 0; o >>= 1) {
        s  += __shfl_xor_sync(0xffffffffu, s,  o);
        s2 += __shfl_xor_sync(0xffffffffu, s2, o);
    }
    float mu  = s * (1.0f / Dz);
    float var = s2 * (1.0f / Dz) - mu * mu;
    float inv = rsqrtf(var + 1e-5f);

    const float2* g2 = (const float2*)gam;
    const float2* b2 = (const float2*)bet;
    __half2* ob = (__half2*)(outp + (size_t)gw * Dz);
    #pragma unroll
    for (int i = 0; i < 2; i++) {
        int p0 = (lane + 32 * i) * 4;      // half2-pair index base
        #pragma unroll
        for (int k = 0; k < 4; k++) {
            float2 gg = g2[p0 + k];
            float2 bb = b2[p0 + k];
            float o0 = (vals[i * 8 + k * 2 + 0] - mu) * inv * gg.x + bb.x;
            float o1 = (vals[i * 8 + k * 2 + 1] - mu) * inv * gg.y + bb.y;
            ob[p0 + k] = __floats2half2_rn(o0, o1);
        }
    }
}

// =================== chunked linear scan, half2-vectorized, CH=32 ==========
__global__ void scan_partial(const __half* __restrict__ xn,
                             const float* __restrict__ decay,
                             float* __restrict__ lend) {
    int idx = blockIdx.x * blockDim.x + threadIdx.x;   // Bz*CH*D2 threads
    int d2 = idx & (D2 - 1);
    int c  = (idx >> 8) & (CH - 1);
    int b  = idx >> 13;
    float2 dl = ((const float2*)decay)[d2];
    float a0 = 1.0f / (1.0f + expf(-dl.x));
    float a1 = 1.0f / (1.0f + expf(-dl.y));
    float na0 = 1.0f - a0, na1 = 1.0f - a1;
    const __half2* p = (const __half2*)(xn + ((size_t)(b * Tz + c * LCH)) * Dz) + d2;
    float s0 = 0.0f, s1 = 0.0f;
    #pragma unroll 8
    for (int t = 0; t < LCH; t++) {
        float2 f = __half22float2(p[(size_t)t * D2]);
        s0 = a0 * s0 + na0 * f.x;
        s1 = a1 * s1 + na1 * f.y;
    }
    ((float2*)lend)[(size_t)(b * CH + c) * D2 + d2] = make_float2(s0, s1);
}

__global__ void scan_carry(const float* __restrict__ lend,
                           const float* __restrict__ decay,
                           float* __restrict__ carry) {
    int idx = blockIdx.x * blockDim.x + threadIdx.x;   // B*Dz threads
    int d = idx & (Dz - 1);
    int b = idx >> 9;
    float a  = 1.0f / (1.0f + expf(-decay[d]));
    float aL = powf(a, (float)LCH);
    float s = 0.0f;
    #pragma unroll
    for (int c = 0; c < CH; c++) {
        int e = (b * CH + c) * Dz + d;
        carry[e] = s;
        s = aL * s + lend[e];
    }
}

// fused: final scan pass (fp16 ss out) + depthwise conv K=5 (fp16 yloc out)
__global__ void scan_final_fused(const __half* __restrict__ xn,
                                 const float* __restrict__ decay,
                                 const float* __restrict__ carry,
                                 const float* __restrict__ cw,
                                 const float* __restrict__ cb,
                                 __half* __restrict__ ssh,
                                 __half* __restrict__ yloc) {
    int idx = blockIdx.x * blockDim.x + threadIdx.x;   // Bz*CH*D2 threads
    int d2 = idx & (D2 - 1);
    int c  = (idx >> 8) & (CH - 1);
    int b  = idx >> 13;
    int d0 = d2 * 2;
    float2 dl = ((const float2*)decay)[d2];
    float a0 = 1.0f / (1.0f + expf(-dl.x));
    float a1 = 1.0f / (1.0f + expf(-dl.y));
    float na0 = 1.0f - a0, na1 = 1.0f - a1;

    float w00 = cw[d0 * Kz + 0], w01 = cw[d0 * Kz + 1], w02 = cw[d0 * Kz + 2];
    float w03 = cw[d0 * Kz + 3], w04 = cw[d0 * Kz + 4];
    float w10 = cw[(d0 + 1) * Kz + 0], w11 = cw[(d0 + 1) * Kz + 1];
    float w12 = cw[(d0 + 1) * Kz + 2], w13 = cw[(d0 + 1) * Kz + 3];
    float w14 = cw[(d0 + 1) * Kz + 4];
    float bb0 = cb[d0], bb1 = cb[d0 + 1];

    int t0 = c * LCH;
    size_t base2 = ((size_t)(b * Tz + t0)) * D2 + d2;   // half2 units
    const __half2* p = (const __half2*)xn + base2;
    float2 xm2 = (t0 >= 2) ? __half22float2(p[-2 * (ptrdiff_t)D2]) : make_float2(0.f, 0.f);
    float2 xm1 = (t0 >= 1) ? __half22float2(p[-1 * (ptrdiff_t)D2]) : make_float2(0.f, 0.f);
    float2 x0  = __half22float2(p[0]);
    float2 x1v = __half22float2(p[(size_t)D2]);

    float2 cr = ((const float2*)carry)[(size_t)(b * CH + c) * D2 + d2];
    float s0 = cr.x, s1 = cr.y;

    __half2* pss = (__half2*)ssh + base2;
    __half2* pyl = (__half2*)yloc + base2;

    #pragma unroll 4
    for (int t = 0; t < LCH; t++) {
        int tg = t0 + t;
        float2 x2 = (tg + 2 < Tz) ? __half22float2(p[(size_t)(t + 2) * D2])
                                  : make_float2(0.f, 0.f);
        s0 = a0 * s0 + na0 * x0.x;
        s1 = a1 * s1 + na1 * x0.y;
        pss[(size_t)t * D2] = __floats2half2_rn(s0, s1);
        float y0 = bb0 + w00 * xm2.x + w01 * xm1.x + w02 * x0.x + w03 * x1v.x + w04 * x2.x;
        float y1 = bb1 + w10 * xm2.y + w11 * xm1.y + w12 * x0.y + w13 * x1v.y + w14 * x2.y;
        pyl[(size_t)t * D2] = __floats2half2_rn(y0, y1);
        xm2 = xm1; xm1 = x0; x0 = x1v; x1v = x2;
    }
}

// =================== weights fp32 -> fp16 (single launch) ===================
#define N0 (Dz * Dz)
#define N1 (HIDz * Dz)
#define N2 (Dz * HIDz)
__global__ void wconv(const float* __restrict__ w0, const float* __restrict__ w1,
                      const float* __restrict__ w2,
                      __half* __restrict__ o0, __half* __restrict__ o1,
                      __half* __restrict__ o2) {
    int i = blockIdx.x * blockDim.x + threadIdx.x;
    if (i < N0)                o0[i]           = __float2half(w0[i]);
    else if (i < N0 + N1)      o1[i - N0]      = __float2half(w1[i - N0]);
    else if (i < N0 + N1 + N2) o2[i - N0 - N1] = __float2half(w2[i - N0 - N1]);
}

// =================== mma.sync fp16 GEMM (BM=128, BN=128, BK=64, occ=2) =====
// C[M,Nc] = A[M,Kc] * W[Nc,Kc]^T.  Both operands K-major.
// 8 warps in 2(M)x4(N), warp tile 64x32. 3-stage cp.async pipeline.
// Mainloop order: ks=0 MMA batch first, then next-slab loads, then ks=1..3.
// kt loop: unroll 2 (bounded — full unroll blows I$, see R7).
// EPI 0: out fp32  = acc + bias + res2h(fp16)            [final: x1h + mlp]
// EPI 1: out fp16  = gelu(acc + bias)                    [mlp hidden]
// EPI 2: out fp16  = acc + bias + res1h(fp16) + res2h(fp16)  [x1h]
#define RSTRIDE 144u                       // smem bytes per row (128 data + 16 pad)
#define A_TILE_B (128u * RSTRIDE)          // 18432
#define W_TILE_B (128u * RSTRIDE)          // 18432
#define STAGE_B (A_TILE_B + W_TILE_B)      // 36864
#define NSTAGE 3
#define GEMM_SMEM (NSTAGE * STAGE_B)       // 110592 -> 2 CTAs/SM

__device__ __forceinline__ void ldm_x4(uint32_t* r, uint32_t addr) {
    asm volatile("ldmatrix.sync.aligned.m8n8.x4.shared.b16 {%0,%1,%2,%3}, [%4];"
                 : "=r"(r[0]), "=r"(r[1]), "=r"(r[2]), "=r"(r[3]) : "r"(addr));
}
__device__ __forceinline__ void mma16816(float* c, const uint32_t* a, const uint32_t* b) {
    asm volatile(
        "mma.sync.aligned.m16n8k16.row.col.f32.f16.f16.f32 "
        "{%0,%1,%2,%3}, {%4,%5,%6,%7}, {%8,%9}, {%0,%1,%2,%3};"
        : "+f"(c[0]), "+f"(c[1]), "+f"(c[2]), "+f"(c[3])
        : "r"(a[0]), "r"(a[1]), "r"(a[2]), "r"(a[3]), "r"(b[0]), "r"(b[1]));
}

template<int EPI, int Nc, int Kc>
__global__ void __launch_bounds__(256, 2)
gemm_mma(const __half* __restrict__ A, const __half* __restrict__ W,
         const float* __restrict__ bias,
         const __half* __restrict__ res1h, const __half* __restrict__ res2h,
         void* __restrict__ outp)
{
    extern __shared__ __align__(128) char smem[];
    const uint32_t sb = smem_u32(smem);
    const int tid  = threadIdx.x;
    const int lane = tid & 31;
    const int wid  = tid >> 5;
    const int warp_m = wid >> 2;        // 0..1  (x64 rows)
    const int warp_n = wid & 3;         // 0..3  (x32 cols)
    constexpr int NK = Kc >> 6;         // K / 64
    constexpr int NB = Nc >> 7;         // N / 128
    const int bn = blockIdx.x % NB;
    const int bm = blockIdx.x / NB;
    constexpr size_t Kb = (size_t)Kc * 2;   // row bytes in gmem

    const char* At = (const char*)A + ((size_t)bm << 7) * Kb;
    const char* Wt = (const char*)W + ((size_t)bn << 7) * Kb;

    // ---- async load of one k-slab (A:128 rows, W:128 rows, 64 k each) ----
    #define LOAD_STAGE(LS) do {                                               \
        uint32_t bufa = sb + (uint32_t)((LS) % NSTAGE) * STAGE_B;             \
        uint32_t bufw = bufa + A_TILE_B;                                      \
        size_t kb = (size_t)(LS) * 128;                                       \
        _Pragma("unroll")                                                     \
        for (int i = 0; i < 4; i++) {                                         \
            int idx = (i << 8) + tid;                                         \
            uint32_t r = (uint32_t)(idx >> 3);                                \
            uint32_t j = (uint32_t)(idx & 7) << 4;                            \
            asm volatile("cp.async.cg.shared.global [%0], [%1], 16;"          \
                :: "r"(bufa + r * RSTRIDE + j),                               \
                   "l"(At + (size_t)r * Kb + kb + j) : "memory");             \
        }                                                                     \
        _Pragma("unroll")                                                     \
        for (int i = 0; i < 4; i++) {                                         \
            int idx = (i << 8) + tid;                                         \
            uint32_t r = (uint32_t)(idx >> 3);                                \
            uint32_t j = (uint32_t)(idx & 7) << 4;                            \
            asm volatile("cp.async.cg.shared.global [%0], [%1], 16;"          \
                :: "r"(bufw + r * RSTRIDE + j),                               \
                   "l"(Wt + (size_t)r * Kb + kb + j) : "memory");             \
        }                                                                     \
        asm volatile("cp.async.commit_group;" ::: "memory");                  \
    } while (0)

    float acc[4][4][4];
    #pragma unroll
    for (int i = 0; i < 4; i++)
        #pragma unroll
        for (int j = 0; j < 4; j++)
            #pragma unroll
            for (int r = 0; r < 4; r++) acc[i][j][r] = 0.0f;

    LOAD_STAGE(0);
    LOAD_STAGE(1);

    // per-lane ldmatrix row/col offsets
    const uint32_t lrow = (uint32_t)(lane & 15);
    const uint32_t lcol = (uint32_t)(lane & 16);   // +16B for k+8 half

    #pragma unroll 2
    for (int kt = 0; kt < NK; kt++) {
        asm volatile("cp.async.wait_group 1;" ::: "memory");
        __syncthreads();

        uint32_t bufa = sb + (uint32_t)(kt % NSTAGE) * STAGE_B;
        uint32_t bufw = bufa + A_TILE_B;
        uint32_t abase = bufa + ((uint32_t)(warp_m * 64) + lrow) * RSTRIDE + lcol;
        uint32_t wbase = bufw + ((uint32_t)(warp_n * 32) + lrow) * RSTRIDE + lcol;

        // ---- ks = 0 first (start the tensor pipe before issuing loads) ----
        {
            uint32_t af[4][4];
            #pragma unroll
            for (int im = 0; im < 4; im++)
                ldm_x4(af[im], abase + (uint32_t)(im * 16) * RSTRIDE);
            uint32_t bf[4][2];
            #pragma unroll
            for (int hn = 0; hn < 2; hn++) {
                uint32_t t[4];
                ldm_x4(t, wbase + (uint32_t)(hn * 16) * RSTRIDE);
                bf[hn * 2 + 0][0] = t[0]; bf[hn * 2 + 0][1] = t[2];
                bf[hn * 2 + 1][0] = t[1]; bf[hn * 2 + 1][1] = t[3];
            }
            #pragma unroll
            for (int im = 0; im < 4; im++)
                #pragma unroll
                for (int j = 0; j < 4; j++)
                    mma16816(acc[im][j], af[im], bf[j]);
        }

        // ---- issue next slab loads, overlapped with remaining ks ----
        if (kt + 2 < NK) {
            LOAD_STAGE(kt + 2);
        } else {
            asm volatile("cp.async.commit_group;" ::: "memory");
        }

        #pragma unroll
        for (int ks = 1; ks < 4; ks++) {
            uint32_t kb2 = (uint32_t)ks * 32;
            uint32_t af[4][4];
            #pragma unroll
            for (int im = 0; im < 4; im++)
                ldm_x4(af[im], abase + (uint32_t)(im * 16) * RSTRIDE + kb2);
            uint32_t bf[4][2];
            #pragma unroll
            for (int hn = 0; hn < 2; hn++) {
                uint32_t t[4];
                ldm_x4(t, wbase + (uint32_t)(hn * 16) * RSTRIDE + kb2);
                bf[hn * 2 + 0][0] = t[0]; bf[hn * 2 + 0][1] = t[2];
                bf[hn * 2 + 1][0] = t[1]; bf[hn * 2 + 1][1] = t[3];
            }
            #pragma unroll
            for (int im = 0; im < 4; im++)
                #pragma unroll
                for (int j = 0; j < 4; j++)
                    mma16816(acc[im][j], af[im], bf[j]);
        }
        // top-of-loop barrier (after wait_group) orders buffer reuse.
    }
    #undef LOAD_STAGE

    // ---- epilogue ----
    const int g   = lane >> 2;
    const int tig = lane & 3;
    #pragma unroll
    for (int im = 0; im < 4; im++) {
        int gm = (bm << 7) + warp_m * 64 + im * 16 + g;
        #pragma unroll
        for (int j = 0; j < 4; j++) {
            int gn = (bn << 7) + warp_n * 32 + j * 8 + tig * 2;
            float bv0 = __ldg(&bias[gn]);
            float bv1 = __ldg(&bias[gn + 1]);
            #pragma unroll
            for (int half = 0; half < 2; half++) {
                int row = gm + half * 8;
                size_t off = (size_t)row * Nc + gn;
                float v0 = acc[im][j][half * 2 + 0] + bv0;
                float v1 = acc[im][j][half * 2 + 1] + bv1;
                if (EPI == 0) {
                    float2 r2 = __half22float2(*(const __half2*)(res2h + off));
                    *(float2*)((float*)outp + off) = make_float2(v0 + r2.x, v1 + r2.y);
                } else if (EPI == 2) {
                    float2 r1 = __half22float2(*(const __half2*)(res1h + off));
                    float2 r2 = __half22float2(*(const __half2*)(res2h + off));
                    *(__half2*)((__half*)outp + off) =
                        __floats2half2_rn(v0 + r1.x + r2.x, v1 + r1.y + r2.y);
                } else {
                    float g0 = 0.5f * v0 * (1.0f + erff(v0 * 0.70710678118654752f));
                    float g1 = 0.5f * v1 * (1.0f + erff(v1 * 0.70710678118654752f));
                    *(__half2*)((__half*)outp + off) = __floats2half2_rn(g0, g1);
                }
            }
        }
    }
}

// =================== launcher ===================
extern "C" void kernel_launch(void* const* d_in, const int* in_sizes, int n_in,
                              void* d_out, int out_size) {
    const float* x       = (const float*)d_in[0];
    const float* decay   = (const float*)d_in[1];
    const float* W_out   = (const float*)d_in[2];
    const float* b_out   = (const float*)d_in[3];
    const float* conv_w  = (const float*)d_in[4];
    const float* conv_b  = (const float*)d_in[5];
    const float* ln1_g   = (const float*)d_in[6];
    const float* ln1_b   = (const float*)d_in[7];
    const float* ln2_g   = (const float*)d_in[8];
    const float* ln2_b   = (const float*)d_in[9];
    const float* W1      = (const float*)d_in[10];
    const float* b1      = (const float*)d_in[11];
    const float* W2      = (const float*)d_in[12];
    const float* b2      = (const float*)d_in[13];
    float* out = (float*)d_out;

    float *lend, *carry;
    __half *xnh, *xh, *x1h, *yloc, *ssh, *xn2h, *hh, *wouth, *w1h, *w2h;
    cudaGetSymbolAddress((void**)&xnh,   g_xnh);
    cudaGetSymbolAddress((void**)&xh,    g_xh);
    cudaGetSymbolAddress((void**)&x1h,   g_x1h);
    cudaGetSymbolAddress((void**)&yloc,  g_yloc);
    cudaGetSymbolAddress((void**)&lend,  g_lend);
    cudaGetSymbolAddress((void**)&carry, g_carry);
    cudaGetSymbolAddress((void**)&ssh,   g_ssh);
    cudaGetSymbolAddress((void**)&xn2h,  g_xn2h);
    cudaGetSymbolAddress((void**)&hh,    g_hh);
    cudaGetSymbolAddress((void**)&wouth, g_wouth);
    cudaGetSymbolAddress((void**)&w1h,   g_w1h);
    cudaGetSymbolAddress((void**)&w2h,   g_w2h);

    cudaFuncSetAttribute((const void*)gemm_mma<2, Dz, Dz>,
                         cudaFuncAttributeMaxDynamicSharedMemorySize, GEMM_SMEM);
    cudaFuncSetAttribute((const void*)gemm_mma<1, HIDz, Dz>,
                         cudaFuncAttributeMaxDynamicSharedMemorySize, GEMM_SMEM);
    cudaFuncSetAttribute((const void*)gemm_mma<0, Dz, HIDz>,
                         cudaFuncAttributeMaxDynamicSharedMemorySize, GEMM_SMEM);

    // weight conversion (single launch)
    wconv<<<(N0 + N1 + N2 + 255) / 256, 256>>>(W_out, W1, W2, wouth, w1h, w2h);

    // 1) xn = LN1(x)  (fp16) + fp16 copy of x for the GEMM1 residual
    ln_kernel<<<NTOK / 8, 256>>>(x, ln1_g, ln1_b, xnh, xh);

    // 2) retention scan (chunked CH=32, half2-vectorized, full grid) + conv
    scan_partial<<<(Bz * CH * D2) / 256, 256>>>(xnh, decay, lend);
    scan_carry<<<(Bz * Dz) / 256, 256>>>(lend, decay, carry);
    scan_final_fused<<<(Bz * CH * D2) / 256, 256>>>(xnh, decay, carry,
                                                    conv_w, conv_b, ssh, yloc);

    // 3) x1h = fp16(xh + yloc + ss @ W_out^T + b_out)
    gemm_mma<2, Dz, Dz><<<(NTOK / 128) * (Dz / 128), 256, GEMM_SMEM>>>(
        ssh, wouth, b_out, xh, yloc, x1h);

    // 4) xn2 = LN2(x1h)  (fp16 in/out)
    ln_kernel_h<<<NTOK / 8, 256>>>(x1h, ln2_g, ln2_b, xn2h);

    // 5) h = gelu(xn2 @ W1^T + b1)  (fp16 out)
    gemm_mma<1, HIDz, Dz><<<(NTOK / 128) * (HIDz / 128), 256, GEMM_SMEM>>>(
        xn2h, w1h, b1, nullptr, nullptr, hh);

    // 6) out = x1h + h @ W2^T + b2  (fp32 out)
    gemm_mma<0, Dz, HIDz><<<(NTOK / 128) * (Dz / 128), 256, GEMM_SMEM>>>(
        hh, w2h, b2, nullptr, x1h, out);
}